// round 2
// baseline (speedup 1.0000x reference)
#include <cuda_runtime.h>

#define NUM_NODES 100000
#define NUM_EDGES 6400000
#define NUM_STEPS 10

// Scratch (allocation-free rule: __device__ globals)
__device__ int2  g_edges[NUM_EDGES];   // packed {src, dst}, int32
__device__ float g_cur[NUM_NODES];
__device__ float g_acc[NUM_NODES];
__device__ float g_surv[NUM_NODES];
__device__ int   g_is64;               // 1 if edge_index buffer is int64

// ---------------------------------------------------------------------------
// Detect edge_index element width. If the buffer is little-endian int64 with
// values in [0, 1e5), every odd 32-bit word is 0. A real int32 index array
// has ~0 probability of 4096 consecutive zero odd-words.
// ---------------------------------------------------------------------------
__global__ void detect_kernel(const int* __restrict__ w) {
    __shared__ int nz;
    if (threadIdx.x == 0) nz = 0;
    __syncthreads();
    for (int i = threadIdx.x; i < 4096; i += blockDim.x) {
        if (w[2 * i + 1] != 0) nz = 1;
    }
    __syncthreads();
    if (threadIdx.x == 0) g_is64 = nz ? 0 : 1;
}

// ---------------------------------------------------------------------------
// Convert edge_index (2, E) of either width -> packed int2 {src, dst}.
// Indices are clamped defensively so a wrong guess can never fault.
// ---------------------------------------------------------------------------
__global__ void convert_edges_kernel(const void* __restrict__ eidx) {
    int i = blockIdx.x * blockDim.x + threadIdx.x;
    if (i >= NUM_EDGES) return;
    int s, d;
    if (g_is64) {
        const long long* e = (const long long*)eidx;
        s = (int)e[i];
        d = (int)e[NUM_EDGES + i];
    } else {
        const int* e = (const int*)eidx;
        s = e[i];
        d = e[NUM_EDGES + i];
    }
    // clamp (no-op when data is sane; prevents faults if assumptions break)
    s = min(max(s, 0), NUM_NODES - 1);
    d = min(max(d, 0), NUM_NODES - 1);
    g_edges[i] = make_int2(s, d);
}

// ---------------------------------------------------------------------------
// Init node state
// ---------------------------------------------------------------------------
__global__ void init_nodes_kernel(const float* __restrict__ x) {
    int n = blockIdx.x * blockDim.x + threadIdx.x;
    if (n >= NUM_NODES) return;
    float xv = x[n];
    g_cur[n]  = xv;
    g_surv[n] = 1.0f - xv;
    g_acc[n]  = 0.0f;
}

// ---------------------------------------------------------------------------
// Edge pass: acc[dst] += prob * cur[src]   (per-step scalar applied later)
// ---------------------------------------------------------------------------
__global__ void edge_kernel(const float* __restrict__ probs) {
    int i = blockIdx.x * blockDim.x + threadIdx.x;
    if (i >= NUM_EDGES) return;
    int2 e = g_edges[i];
    float m = __ldg(&g_cur[e.x]) * probs[i];
    atomicAdd(&g_acc[e.y], m);
}

// ---------------------------------------------------------------------------
// Node pass: cur = scale*acc + bias; surv *= (1-cur); acc = 0.
// Last step writes clipped output.
// ---------------------------------------------------------------------------
__global__ void node_kernel(const float* __restrict__ time_decay,
                            const float* __restrict__ edge_weight,
                            const float* __restrict__ node_bias,
                            int step, int is_last,
                            float* __restrict__ out) {
    int n = blockIdx.x * blockDim.x + threadIdx.x;
    if (n >= NUM_NODES) return;

    float td = time_decay[step];
    float scale = edge_weight[step] * expf(-(td * td));
    float bias = node_bias[0];

    float cur = scale * g_acc[n] + bias;
    g_acc[n] = 0.0f;
    g_cur[n] = cur;
    float surv = g_surv[n] * (1.0f - cur);
    g_surv[n] = surv;

    if (is_last) {
        float fi = 1.0f - surv;
        out[n] = fminf(fmaxf(fi, 0.0f), 1.0f);
    }
}

// ---------------------------------------------------------------------------
// Launch
// Inputs: 0=x(f32,100000), 1=edge_index(2x6.4M, int32 or int64),
//         2=edge_probs(f32,6.4M), 3=time_decay(f32,10),
//         4=node_bias(f32 scalar), 5=edge_weight(f32,10)
// ---------------------------------------------------------------------------
extern "C" void kernel_launch(void* const* d_in, const int* in_sizes, int n_in,
                              void* d_out, int out_size) {
    const float* x     = (const float*)d_in[0];
    const void*  eidx  = d_in[1];
    const float* probs = (const float*)d_in[2];
    const float* td    = (const float*)d_in[3];
    const float* nb    = (const float*)d_in[4];
    const float* ew    = (const float*)d_in[5];
    float*       out   = (float*)d_out;

    const int TB = 256;

    detect_kernel<<<1, 256>>>((const int*)eidx);
    convert_edges_kernel<<<(NUM_EDGES + TB - 1) / TB, TB>>>(eidx);
    init_nodes_kernel<<<(NUM_NODES + TB - 1) / TB, TB>>>(x);

    int eblocks = (NUM_EDGES + TB - 1) / TB;
    int nblocks = (NUM_NODES + TB - 1) / TB;

    for (int step = 0; step < NUM_STEPS; step++) {
        edge_kernel<<<eblocks, TB>>>(probs);
        node_kernel<<<nblocks, TB>>>(td, ew, nb, step,
                                     (step == NUM_STEPS - 1) ? 1 : 0, out);
    }
}

// round 4
// speedup vs baseline: 1.2367x; 1.2367x over previous
#include <cuda_runtime.h>

#define NUM_NODES 100000
#define NUM_EDGES 6400000
#define NUM_STEPS 10
#define SCAN_BLK 1024
#define NUM_SCAN_BLOCKS ((NUM_NODES + SCAN_BLK - 1) / SCAN_BLK)   // 98

// Scratch (allocation-free rule: __device__ globals)
__device__ int2  g_edges[NUM_EDGES];          // packed {src, dst}
__device__ int2  g_sp[NUM_EDGES];             // {src, prob-bits}, sorted by dst
__device__ int   g_count[NUM_NODES];
__device__ int   g_rowptr[NUM_NODES + 1];
__device__ int   g_cursor[NUM_NODES];
__device__ int   g_blocksum[NUM_SCAN_BLOCKS];
__device__ float g_curA[NUM_NODES];
__device__ float g_curB[NUM_NODES];
__device__ float g_surv[NUM_NODES];
__device__ int   g_is64;

// ---------------------------------------------------------------------------
// Detect edge_index element width (int64 delivered vs int32): int64 values
// < 1e5 have every odd 32-bit word == 0.
// ---------------------------------------------------------------------------
__global__ void detect_kernel(const int* __restrict__ w) {
    __shared__ int nz;
    if (threadIdx.x == 0) nz = 0;
    __syncthreads();
    for (int i = threadIdx.x; i < 4096; i += blockDim.x)
        if (w[2 * i + 1] != 0) nz = 1;
    __syncthreads();
    if (threadIdx.x == 0) g_is64 = nz ? 0 : 1;
}

__global__ void zero_counts_kernel() {
    int i = blockIdx.x * blockDim.x + threadIdx.x;
    if (i < NUM_NODES) g_count[i] = 0;
}

// ---------------------------------------------------------------------------
// Convert edge_index -> packed int2 AND histogram dst degrees (fused).
// ---------------------------------------------------------------------------
__global__ void convert_hist_kernel(const void* __restrict__ eidx) {
    int i = blockIdx.x * blockDim.x + threadIdx.x;
    if (i >= NUM_EDGES) return;
    int s, d;
    if (g_is64) {
        const long long* e = (const long long*)eidx;
        s = (int)e[i];
        d = (int)e[NUM_EDGES + i];
    } else {
        const int* e = (const int*)eidx;
        s = e[i];
        d = e[NUM_EDGES + i];
    }
    s = min(max(s, 0), NUM_NODES - 1);
    d = min(max(d, 0), NUM_NODES - 1);
    g_edges[i] = make_int2(s, d);
    atomicAdd(&g_count[d], 1);
}

// ---------------------------------------------------------------------------
// 3-phase exclusive scan of g_count -> g_rowptr (and g_cursor copy).
// ---------------------------------------------------------------------------
__global__ void scan1_kernel() {
    __shared__ int s[SCAN_BLK];
    int tid = threadIdx.x;
    int i = blockIdx.x * SCAN_BLK + tid;
    int v = (i < NUM_NODES) ? g_count[i] : 0;
    s[tid] = v;
    __syncthreads();
    #pragma unroll
    for (int off = 1; off < SCAN_BLK; off <<= 1) {
        int t = (tid >= off) ? s[tid - off] : 0;
        __syncthreads();
        s[tid] += t;
        __syncthreads();
    }
    if (i < NUM_NODES) g_rowptr[i] = s[tid] - v;   // exclusive, sans block offset
    if (tid == SCAN_BLK - 1) g_blocksum[blockIdx.x] = s[tid];
}

__global__ void scan2_kernel() {
    if (threadIdx.x == 0) {
        int run = 0;
        for (int b = 0; b < NUM_SCAN_BLOCKS; b++) {
            int t = g_blocksum[b];
            g_blocksum[b] = run;
            run += t;
        }
        g_rowptr[NUM_NODES] = NUM_EDGES;
    }
}

__global__ void scan3_kernel() {
    int i = blockIdx.x * blockDim.x + threadIdx.x;
    if (i >= NUM_NODES) return;
    int r = g_rowptr[i] + g_blocksum[i / SCAN_BLK];
    g_rowptr[i] = r;
    g_cursor[i] = r;
}

// ---------------------------------------------------------------------------
// Scatter edges into dst-sorted CSR payload: {src, prob}.
// ---------------------------------------------------------------------------
__global__ void scatter_kernel(const float* __restrict__ probs) {
    int i = blockIdx.x * blockDim.x + threadIdx.x;
    if (i >= NUM_EDGES) return;
    int2 e = g_edges[i];
    float p = probs[i];
    int pos = atomicAdd(&g_cursor[e.y], 1);
    g_sp[pos] = make_int2(e.x, __float_as_int(p));
}

__global__ void init_nodes_kernel(const float* __restrict__ x) {
    int n = blockIdx.x * blockDim.x + threadIdx.x;
    if (n >= NUM_NODES) return;
    float xv = x[n];
    g_curA[n] = xv;
    g_surv[n] = 1.0f - xv;
}

// ---------------------------------------------------------------------------
// Fused step: warp-per-row segmented SpMV (no atomics) + node update.
// Buffer parity resolved IN DEVICE CODE (host-side &g_curA is invalid!).
//   c = scale * sum(prob*cur[src]) + bias
//   curn[row] = c;  surv[row] *= (1-c);  last step: out = clip(1-surv)
// ---------------------------------------------------------------------------
__global__ void spmv_step_kernel(const float* __restrict__ td,
                                 const float* __restrict__ ew,
                                 const float* __restrict__ nb,
                                 int step, int is_last,
                                 float* __restrict__ out) {
    int w = (blockIdx.x * blockDim.x + threadIdx.x) >> 5;
    int lane = threadIdx.x & 31;
    if (w >= NUM_NODES) return;

    const float* cur  = (step & 1) ? g_curB : g_curA;
    float*       curn = (step & 1) ? g_curA : g_curB;

    int start = g_rowptr[w];
    int end   = g_rowptr[w + 1];

    float sum = 0.0f;
    for (int j = start + lane; j < end; j += 32) {
        int2 e = g_sp[j];
        sum += __ldg(&cur[e.x]) * __int_as_float(e.y);
    }
    #pragma unroll
    for (int o = 16; o; o >>= 1)
        sum += __shfl_xor_sync(0xffffffffu, sum, o);

    if (lane == 0) {
        float tdv = td[step];
        float scale = ew[step] * expf(-(tdv * tdv));
        float c = scale * sum + nb[0];
        curn[w] = c;
        float sv = g_surv[w] * (1.0f - c);
        g_surv[w] = sv;
        if (is_last) {
            float fi = 1.0f - sv;
            out[w] = fminf(fmaxf(fi, 0.0f), 1.0f);
        }
    }
}

// ---------------------------------------------------------------------------
// Launch
// ---------------------------------------------------------------------------
extern "C" void kernel_launch(void* const* d_in, const int* in_sizes, int n_in,
                              void* d_out, int out_size) {
    const float* x     = (const float*)d_in[0];
    const void*  eidx  = d_in[1];
    const float* probs = (const float*)d_in[2];
    const float* td    = (const float*)d_in[3];
    const float* nb    = (const float*)d_in[4];
    const float* ew    = (const float*)d_in[5];
    float*       out   = (float*)d_out;

    const int TB = 256;
    int eblocks = (NUM_EDGES + TB - 1) / TB;
    int nblocks = (NUM_NODES + TB - 1) / TB;

    detect_kernel<<<1, 256>>>((const int*)eidx);
    zero_counts_kernel<<<nblocks, TB>>>();
    convert_hist_kernel<<<eblocks, TB>>>(eidx);
    scan1_kernel<<<NUM_SCAN_BLOCKS, SCAN_BLK>>>();
    scan2_kernel<<<1, 32>>>();
    scan3_kernel<<<nblocks, TB>>>();
    scatter_kernel<<<eblocks, TB>>>(probs);
    init_nodes_kernel<<<nblocks, TB>>>(x);

    // warp per row: 100000 warps -> 12500 blocks of 256 (8 warps)
    int sblocks = (NUM_NODES * 32 + TB - 1) / TB;
    for (int step = 0; step < NUM_STEPS; step++) {
        spmv_step_kernel<<<sblocks, TB>>>(td, ew, nb, step,
                                          (step == NUM_STEPS - 1) ? 1 : 0, out);
    }
}

// round 5
// speedup vs baseline: 1.5000x; 1.2129x over previous
#include <cuda_runtime.h>

#define NUM_NODES 100000
#define NUM_EDGES 6400000
#define NUM_STEPS 10

#define TILE 10000                 // dst nodes per tile (40KB smem acc)
#define NTILES 10                  // NUM_NODES / TILE
#define CTAS_PER_TILE 15
#define STEP_TPB 1024

#define NBINS (NTILES * NUM_NODES) // 1,000,000 bins: key = tile*NUM_NODES + src
#define SCAN_BLK 1024
#define NSB ((NBINS + SCAN_BLK - 1) / SCAN_BLK)   // 977

// Scratch (allocation-free rule: __device__ globals)
__device__ int2  g_edges[NUM_EDGES];      // {bin, packed src<<14|dst_local}
__device__ uint2 g_sp2[NUM_EDGES];        // {packed key, prob-bits}, sorted by bin
__device__ int   g_bins[NBINS];
__device__ int   g_binptr[NBINS + 1];
__device__ int   g_cursor[NBINS];
__device__ int   g_blocksum[NSB];
__device__ float g_curA[NUM_NODES];
__device__ float g_curB[NUM_NODES];
__device__ float g_surv[NUM_NODES];
__device__ float g_acc[NUM_NODES];
__device__ int   g_is64;

// ---------------------------------------------------------------------------
// Detect edge_index element width (int64 vs int32): int64 values < 1e5 have
// every odd 32-bit word == 0.
// ---------------------------------------------------------------------------
__global__ void detect_kernel(const int* __restrict__ w) {
    __shared__ int nz;
    if (threadIdx.x == 0) nz = 0;
    __syncthreads();
    for (int i = threadIdx.x; i < 4096; i += blockDim.x)
        if (w[2 * i + 1] != 0) nz = 1;
    __syncthreads();
    if (threadIdx.x == 0) g_is64 = nz ? 0 : 1;
}

__global__ void zero_bins_kernel() {
    int i = blockIdx.x * blockDim.x + threadIdx.x;
    if (i < NBINS) g_bins[i] = 0;
}

// ---------------------------------------------------------------------------
// Convert edges -> {bin, packed} AND histogram bins.
// bin = dst_tile * NUM_NODES + src  (primary: tile, secondary: src)
// packed = src << 14 | dst_local    (src 17 bits, dst_local < 16384)
// ---------------------------------------------------------------------------
__global__ void convert_hist_kernel(const void* __restrict__ eidx) {
    int i = blockIdx.x * blockDim.x + threadIdx.x;
    if (i >= NUM_EDGES) return;
    int s, d;
    if (g_is64) {
        const long long* e = (const long long*)eidx;
        s = (int)e[i];
        d = (int)e[NUM_EDGES + i];
    } else {
        const int* e = (const int*)eidx;
        s = e[i];
        d = e[NUM_EDGES + i];
    }
    s = min(max(s, 0), NUM_NODES - 1);
    d = min(max(d, 0), NUM_NODES - 1);
    int tile = d / TILE;
    int dl   = d - tile * TILE;
    int bin  = tile * NUM_NODES + s;
    g_edges[i] = make_int2(bin, (s << 14) | dl);
    atomicAdd(&g_bins[bin], 1);
}

// ---------------------------------------------------------------------------
// 3-phase exclusive scan of g_bins -> g_binptr (+ cursor copy)
// ---------------------------------------------------------------------------
__global__ void scan1_kernel() {
    __shared__ int s[SCAN_BLK];
    int tid = threadIdx.x;
    int i = blockIdx.x * SCAN_BLK + tid;
    int v = (i < NBINS) ? g_bins[i] : 0;
    s[tid] = v;
    __syncthreads();
    #pragma unroll
    for (int off = 1; off < SCAN_BLK; off <<= 1) {
        int t = (tid >= off) ? s[tid - off] : 0;
        __syncthreads();
        s[tid] += t;
        __syncthreads();
    }
    if (i < NBINS) g_binptr[i] = s[tid] - v;   // exclusive, sans block offset
    if (tid == SCAN_BLK - 1) g_blocksum[blockIdx.x] = s[tid];
}

__global__ void scan2_kernel() {
    __shared__ int s[SCAN_BLK];
    int tid = threadIdx.x;
    int v = (tid < NSB) ? g_blocksum[tid] : 0;
    s[tid] = v;
    __syncthreads();
    #pragma unroll
    for (int off = 1; off < SCAN_BLK; off <<= 1) {
        int t = (tid >= off) ? s[tid - off] : 0;
        __syncthreads();
        s[tid] += t;
        __syncthreads();
    }
    if (tid < NSB) g_blocksum[tid] = s[tid] - v;  // exclusive block offsets
    if (tid == 0) g_binptr[NBINS] = NUM_EDGES;
}

__global__ void scan3_kernel() {
    int i = blockIdx.x * blockDim.x + threadIdx.x;
    if (i >= NBINS) return;
    int r = g_binptr[i] + g_blocksum[i / SCAN_BLK];
    g_binptr[i] = r;
    g_cursor[i] = r;
}

// ---------------------------------------------------------------------------
// Scatter into (tile, src)-sorted order.
// ---------------------------------------------------------------------------
__global__ void scatter_kernel(const float* __restrict__ probs) {
    int i = blockIdx.x * blockDim.x + threadIdx.x;
    if (i >= NUM_EDGES) return;
    int2 e = g_edges[i];
    float p = probs[i];
    int pos = atomicAdd(&g_cursor[e.x], 1);
    g_sp2[pos] = make_uint2((unsigned)e.y, (unsigned)__float_as_int(p));
}

__global__ void init_nodes_kernel(const float* __restrict__ x) {
    int n = blockIdx.x * blockDim.x + threadIdx.x;
    if (n >= NUM_NODES) return;
    float xv = x[n];
    g_curA[n] = xv;
    g_surv[n] = 1.0f - xv;
    g_acc[n]  = 0.0f;
}

// ---------------------------------------------------------------------------
// Per-step edge pass: one dst tile per CTA group, smem accumulation.
// srcs ascend within a tile -> coalesced cur[src] gathers.
// ---------------------------------------------------------------------------
__global__ void __launch_bounds__(STEP_TPB)
spmv_tile_kernel(int step) {
    __shared__ float acc[TILE];
    int tile = blockIdx.x / CTAS_PER_TILE;
    int sub  = blockIdx.x % CTAS_PER_TILE;

    for (int i = threadIdx.x; i < TILE; i += STEP_TPB) acc[i] = 0.0f;
    __syncthreads();

    const float* cur = (step & 1) ? g_curB : g_curA;

    int start = g_binptr[tile * NUM_NODES];
    int end   = g_binptr[(tile + 1) * NUM_NODES];
    int n = end - start;
    int per = (n + CTAS_PER_TILE - 1) / CTAS_PER_TILE;
    int a = start + sub * per;
    int b = min(a + per, end);

    for (int j = a + threadIdx.x; j < b; j += STEP_TPB) {
        uint2 e = g_sp2[j];
        int src = (int)(e.x >> 14);
        int dl  = (int)(e.x & 16383u);
        atomicAdd(&acc[dl], __ldg(&cur[src]) * __int_as_float((int)e.y));
    }
    __syncthreads();

    int base = tile * TILE;
    for (int i = threadIdx.x; i < TILE; i += STEP_TPB) {
        float v = acc[i];
        if (v != 0.0f) atomicAdd(&g_acc[base + i], v);
    }
}

// ---------------------------------------------------------------------------
// Per-step node pass: cur' = scale*acc + bias; surv *= (1-cur'); acc = 0.
// Buffer parity resolved in device code.
// ---------------------------------------------------------------------------
__global__ void node_kernel(const float* __restrict__ td,
                            const float* __restrict__ ew,
                            const float* __restrict__ nb,
                            int step, int is_last,
                            float* __restrict__ out) {
    int n = blockIdx.x * blockDim.x + threadIdx.x;
    if (n >= NUM_NODES) return;

    float* curn = (step & 1) ? g_curA : g_curB;

    float tdv = td[step];
    float scale = ew[step] * expf(-(tdv * tdv));
    float c = scale * g_acc[n] + nb[0];
    g_acc[n] = 0.0f;
    curn[n] = c;
    float sv = g_surv[n] * (1.0f - c);
    g_surv[n] = sv;
    if (is_last) {
        float fi = 1.0f - sv;
        out[n] = fminf(fmaxf(fi, 0.0f), 1.0f);
    }
}

// ---------------------------------------------------------------------------
// Launch
// ---------------------------------------------------------------------------
extern "C" void kernel_launch(void* const* d_in, const int* in_sizes, int n_in,
                              void* d_out, int out_size) {
    const float* x     = (const float*)d_in[0];
    const void*  eidx  = d_in[1];
    const float* probs = (const float*)d_in[2];
    const float* td    = (const float*)d_in[3];
    const float* nb    = (const float*)d_in[4];
    const float* ew    = (const float*)d_in[5];
    float*       out   = (float*)d_out;

    const int TB = 256;
    int eblocks = (NUM_EDGES + TB - 1) / TB;
    int nblocks = (NUM_NODES + TB - 1) / TB;
    int bblocks = (NBINS + TB - 1) / TB;

    detect_kernel<<<1, 256>>>((const int*)eidx);
    zero_bins_kernel<<<bblocks, TB>>>();
    convert_hist_kernel<<<eblocks, TB>>>(eidx);
    scan1_kernel<<<NSB, SCAN_BLK>>>();
    scan2_kernel<<<1, SCAN_BLK>>>();
    scan3_kernel<<<bblocks, TB>>>();
    scatter_kernel<<<eblocks, TB>>>(probs);
    init_nodes_kernel<<<nblocks, TB>>>(x);

    for (int step = 0; step < NUM_STEPS; step++) {
        spmv_tile_kernel<<<NTILES * CTAS_PER_TILE, STEP_TPB>>>(step);
        node_kernel<<<nblocks, TB>>>(td, ew, nb, step,
                                     (step == NUM_STEPS - 1) ? 1 : 0, out);
    }
}